// round 1
// baseline (speedup 1.0000x reference)
#include <cuda_runtime.h>
#include <cstdint>

#define BB_ 8
#define CC_ 256
#define HH_ 128
#define WW_ 128
#define NPIX (BB_*HH_*WW_)   // 131072
#define HW_ (HH_*WW_)        // 16384

// Bit-packed scratch (allocation-free __device__ globals).
// Layout: per pixel, 8 uint32 words (= 2 uint4); bit i of word wd = channel wd*32+i, 1 <=> value >= 0.
__device__ uint4 g_xbits[NPIX*2];       // 4 MB  binarized input
__device__ uint4 g_mbits[NPIX*2];       // 4 MB  binarized mid (concat of 4 branches)
__device__ uint4 g_wb  [4*64*5*2];      // branch weights: [br][o][k][2]
__device__ uint4 g_wcb [256*9*2];       // main conv weights: [o][t][2], t = kh*3+kw

__device__ __forceinline__ int pdot8(uint4 a0, uint4 a1, uint4 b0, uint4 b1) {
    return __popc(a0.x^b0.x) + __popc(a0.y^b0.y) + __popc(a0.z^b0.z) + __popc(a0.w^b0.w)
         + __popc(a1.x^b1.x) + __popc(a1.y^b1.y) + __popc(a1.z^b1.z) + __popc(a1.w^b1.w);
}

// ---------------------------------------------------------------------------
// Pack binarized x into bits. 1M threads; thread = (word, pixel), pixel fastest
// so the 32 strided channel loads are coalesced across the warp.
__global__ __launch_bounds__(256) void pack_x(const float* __restrict__ x) {
    int tid = blockIdx.x*256 + threadIdx.x;
    int wd  = tid >> 17;            // 0..7
    int pix = tid & (NPIX-1);       // b*16384 + h*128 + w
    int b   = pix >> 14;
    int hw  = pix & (HW_-1);
    const float* p = x + ((size_t)(b*CC_ + wd*32))*HW_ + hw;
    unsigned bits = 0;
    #pragma unroll
    for (int i = 0; i < 32; i++)
        if (p[(size_t)i*HW_] >= 0.f) bits |= (1u << i);
    ((unsigned*)g_xbits)[pix*8 + wd] = bits;
}

// ---------------------------------------------------------------------------
// Pack binarized weights (branch + main). 28672 threads total.
__global__ __launch_bounds__(256) void pack_w(
    const float* __restrict__ w1, const float* __restrict__ w2,
    const float* __restrict__ w3, const float* __restrict__ w4,
    const float* __restrict__ wc)
{
    int tid = blockIdx.x*256 + threadIdx.x;
    if (tid < 4*64*5*8) {
        int idx = tid;
        int wd = idx & 7;  idx >>= 3;
        int k  = idx % 5;  idx /= 5;
        int o  = idx % 64;
        int br = idx / 64;
        const float* src = (br==0) ? w1 : (br==1) ? w2 : (br==2) ? w3 : w4;
        unsigned bits = 0;
        #pragma unroll
        for (int i = 0; i < 32; i++) {
            int c = wd*32 + i;
            float v = src[(o*CC_ + c)*5 + k];   // [o][c][0][k] / [o][c][k][0]
            if (v >= 0.f) bits |= (1u << i);
        }
        ((unsigned*)g_wb)[tid] = bits;
    } else {
        int j = tid - 4*64*5*8;
        if (j < 256*9*8) {
            int wd = j & 7;
            int t  = (j >> 3) % 9;
            int o  = (j >> 3) / 9;
            unsigned bits = 0;
            #pragma unroll
            for (int i = 0; i < 32; i++) {
                int c = wd*32 + i;
                float v = wc[(o*CC_ + c)*9 + t];   // [o][c][kh][kw], t = kh*3+kw
                if (v >= 0.f) bits |= (1u << i);
            }
            ((unsigned*)g_wcb)[j] = bits;
        }
    }
}

// ---------------------------------------------------------------------------
// Branch convs -> sign bits of prelu(concat). Block tile: 32w x 8h pixels.
// 256 threads = 256 concat channels; warp w -> channels [32w, 32w+32):
//   branch = warp/2, o = (warp&1)*32 + lane.  Ballot packs one mid word/warp.
__global__ __launch_bounds__(256) void branch_conv(
    const float* __restrict__ b1, const float* __restrict__ b2,
    const float* __restrict__ b3, const float* __restrict__ b4,
    const float* __restrict__ a1p)
{
    __shared__ uint4 xt[16*40*2];   // rows h0-4..h0+11, cols w0-4..w0+35 (20 KB)
    const int w0 = blockIdx.x*32, h0 = blockIdx.y*8, bb = blockIdx.z;
    const int tid = threadIdx.x;

    for (int i = tid; i < 16*40; i += 256) {
        int r = i / 40, cc = i % 40;
        int h = h0 - 4 + r, w = w0 - 4 + cc;
        uint4 v0 = make_uint4(0,0,0,0), v1 = v0;
        if (h >= 0 && h < HH_ && w >= 0 && w < WW_) {
            const uint4* src = g_xbits + ((bb*HH_ + h)*WW_ + w)*2;
            v0 = src[0]; v1 = src[1];
        }
        xt[i*2] = v0; xt[i*2+1] = v1;
    }
    __syncthreads();

    const int warp = tid >> 5, lane = tid & 31;
    const int br   = warp >> 1;
    const int o    = (warp & 1)*32 + lane;
    const float bias = ((br==0) ? b1 : (br==1) ? b2 : (br==2) ? b3 : b4)[o];
    const float a1   = a1p[0];
    // tap pattern: (dh,dw) = (k-2)*(sh,sw)
    const int sh = (br >= 2) ? ((br == 2) ? 1 : 2) : 0;
    const int sw = (br <  2) ? ((br == 0) ? 1 : 2) : 0;

    uint4 wr[10];
    {
        const uint4* wsrc = g_wb + ((br*64 + o)*5)*2;
        #pragma unroll
        for (int i = 0; i < 10; i++) wr[i] = wsrc[i];
    }

    unsigned* mout = (unsigned*)g_mbits;
    for (int p = 0; p < 256; p++) {
        int r = p >> 5, cl = p & 31;
        int h = h0 + r, w = w0 + cl;
        int s = 0, nv = 0;
        #pragma unroll
        for (int k = 0; k < 5; k++) {
            int ddh = (k-2)*sh, ddw = (k-2)*sw;
            int hh = h + ddh, ww = w + ddw;
            if (hh >= 0 && hh < HH_ && ww >= 0 && ww < WW_) {   // warp-uniform
                nv++;
                int si = ((r + 4 + ddh)*40 + (cl + 4 + ddw))*2;
                s += pdot8(xt[si], xt[si+1], wr[2*k], wr[2*k+1]);
            }
        }
        float v  = (float)(256*nv - 2*s) + bias;
        float pr = (v >= 0.f) ? v : a1*v;
        unsigned m = __ballot_sync(0xffffffffu, pr >= 0.f);
        if (lane == 0) mout[((bb*HH_ + h)*WW_ + w)*8 + warp] = m;
    }
}

// ---------------------------------------------------------------------------
// Main 3x3 conv + bias + prelu + residual. Block tile: 1 row x 32 pixels.
// 256 threads = 256 out channels; results staged in padded smem so the
// NCHW fp32 store + residual read are coalesced.
__global__ __launch_bounds__(256) void main_conv(
    const float* __restrict__ x, const float* __restrict__ bc,
    const float* __restrict__ a2p, float* __restrict__ out)
{
    __shared__ uint4 xt[3*34*2];        // rows h-1..h+1, cols w0-1..w0+32 (3.2 KB)
    __shared__ int   sInt[256*33];      // [o][32] padded to 33 (33.8 KB)
    const int w0 = blockIdx.x*32, h = blockIdx.y, bb = blockIdx.z;
    const int tid = threadIdx.x;        // = out channel o

    for (int i = tid; i < 3*34; i += 256) {
        int r = i / 34, cc = i % 34;
        int hh = h - 1 + r, ww = w0 - 1 + cc;
        uint4 v0 = make_uint4(0,0,0,0), v1 = v0;
        if (hh >= 0 && hh < HH_ && ww >= 0 && ww < WW_) {
            const uint4* src = g_mbits + ((bb*HH_ + hh)*WW_ + ww)*2;
            v0 = src[0]; v1 = src[1];
        }
        xt[i*2] = v0; xt[i*2+1] = v1;
    }
    __syncthreads();

    uint4 wr[18];
    {
        const uint4* wsrc = g_wcb + tid*18;
        #pragma unroll
        for (int i = 0; i < 18; i++) wr[i] = wsrc[i];
    }

    for (int p = 0; p < 32; p++) {
        int w = w0 + p;
        int s = 0, nv = 0;
        #pragma unroll
        for (int t = 0; t < 9; t++) {
            int ddh = t/3 - 1, ddw = t%3 - 1;
            int hh = h + ddh, ww = w + ddw;
            if (hh >= 0 && hh < HH_ && ww >= 0 && ww < WW_) {   // warp-uniform
                nv++;
                int si = ((ddh + 1)*34 + (p + 1 + ddw))*2;
                s += pdot8(xt[si], xt[si+1], wr[2*t], wr[2*t+1]);
            }
        }
        sInt[tid*33 + p] = 256*nv - 2*s;
    }
    __syncthreads();

    const float a2 = a2p[0];
    for (int i = 0; i < 32; i++) {
        int e = i*256 + tid;
        int o = e >> 5, wl = e & 31;
        float v = (float)sInt[o*33 + wl] + bc[o];
        v = (v >= 0.f) ? v : a2*v;
        size_t xi = (((size_t)bb*CC_ + o)*HH_ + h)*WW_ + w0 + wl;
        out[xi] = v + x[xi];
    }
}

// ---------------------------------------------------------------------------
extern "C" void kernel_launch(void* const* d_in, const int* in_sizes, int n_in,
                              void* d_out, int out_size) {
    const float* x  = (const float*)d_in[0];
    const float* w1 = (const float*)d_in[1];
    const float* b1 = (const float*)d_in[2];
    const float* w2 = (const float*)d_in[3];
    const float* b2 = (const float*)d_in[4];
    const float* w3 = (const float*)d_in[5];
    const float* b3 = (const float*)d_in[6];
    const float* w4 = (const float*)d_in[7];
    const float* b4 = (const float*)d_in[8];
    const float* a1 = (const float*)d_in[9];
    const float* wc = (const float*)d_in[10];
    const float* bc = (const float*)d_in[11];
    const float* a2 = (const float*)d_in[12];
    float* out = (float*)d_out;

    pack_x<<<4096, 256>>>(x);
    pack_w<<<112, 256>>>(w1, w2, w3, w4, wc);
    branch_conv<<<dim3(4,16,8), 256>>>(b1, b2, b3, b4, a1);
    main_conv<<<dim3(4,128,8), 256>>>(x, bc, a2, out);
}

// round 2
// speedup vs baseline: 1.0028x; 1.0028x over previous
#include <cuda_runtime.h>
#include <cstdint>

#define BB_ 8
#define CC_ 256
#define HH_ 128
#define WW_ 128
#define NPIX (BB_*HH_*WW_)   // 131072
#define HW_ (HH_*WW_)        // 16384

// Bit-packed scratch (allocation-free __device__ globals).
// Layout: per pixel, 8 uint32 words (= 2 uint4); bit i of word wd = channel wd*32+i, 1 <=> value >= 0.
__device__ uint4 g_xbits[NPIX*2];       // 4 MB  binarized input
__device__ uint4 g_mbits[NPIX*2];       // 4 MB  binarized mid (concat of 4 branches)
__device__ uint4 g_wb  [4*64*5*2];      // branch weights: [br][o][k][2]
__device__ uint4 g_wcb [256*9*2];       // main conv weights: [o][t][2], t = kh*3+kw

__device__ __forceinline__ int pdot8(uint4 a0, uint4 a1, uint4 b0, uint4 b1) {
    return __popc(a0.x^b0.x) + __popc(a0.y^b0.y) + __popc(a0.z^b0.z) + __popc(a0.w^b0.w)
         + __popc(a1.x^b1.x) + __popc(a1.y^b1.y) + __popc(a1.z^b1.z) + __popc(a1.w^b1.w);
}

// ---------------------------------------------------------------------------
// Pack binarized x into bits. 1M threads; thread = (word, pixel), pixel fastest
// so the 32 strided channel loads are coalesced across the warp.
__global__ __launch_bounds__(256) void pack_x(const float* __restrict__ x) {
    int tid = blockIdx.x*256 + threadIdx.x;
    int wd  = tid >> 17;            // 0..7
    int pix = tid & (NPIX-1);       // b*16384 + h*128 + w
    int b   = pix >> 14;
    int hw  = pix & (HW_-1);
    const float* p = x + ((size_t)(b*CC_ + wd*32))*HW_ + hw;
    unsigned bits = 0;
    #pragma unroll
    for (int i = 0; i < 32; i++)
        if (p[(size_t)i*HW_] >= 0.f) bits |= (1u << i);
    ((unsigned*)g_xbits)[pix*8 + wd] = bits;
}

// ---------------------------------------------------------------------------
// Pack binarized weights (branch + main). 28672 threads total.
__global__ __launch_bounds__(256) void pack_w(
    const float* __restrict__ w1, const float* __restrict__ w2,
    const float* __restrict__ w3, const float* __restrict__ w4,
    const float* __restrict__ wc)
{
    int tid = blockIdx.x*256 + threadIdx.x;
    if (tid < 4*64*5*8) {
        int idx = tid;
        int wd = idx & 7;  idx >>= 3;
        int k  = idx % 5;  idx /= 5;
        int o  = idx % 64;
        int br = idx / 64;
        const float* src = (br==0) ? w1 : (br==1) ? w2 : (br==2) ? w3 : w4;
        unsigned bits = 0;
        #pragma unroll
        for (int i = 0; i < 32; i++) {
            int c = wd*32 + i;
            float v = src[(o*CC_ + c)*5 + k];   // [o][c][0][k] / [o][c][k][0]
            if (v >= 0.f) bits |= (1u << i);
        }
        ((unsigned*)g_wb)[tid] = bits;
    } else {
        int j = tid - 4*64*5*8;
        if (j < 256*9*8) {
            int wd = j & 7;
            int t  = (j >> 3) % 9;
            int o  = (j >> 3) / 9;
            unsigned bits = 0;
            #pragma unroll
            for (int i = 0; i < 32; i++) {
                int c = wd*32 + i;
                float v = wc[(o*CC_ + c)*9 + t];   // [o][c][kh][kw], t = kh*3+kw
                if (v >= 0.f) bits |= (1u << i);
            }
            ((unsigned*)g_wcb)[j] = bits;
        }
    }
}

// ---------------------------------------------------------------------------
// Branch convs -> sign bits of prelu(concat). Block tile: 32w x 8h pixels.
// 256 threads = 256 concat channels; warp w -> channels [32w, 32w+32):
//   branch = warp/2, o = (warp&1)*32 + lane.  Ballot packs one mid word/warp.
__global__ __launch_bounds__(256) void branch_conv(
    const float* __restrict__ b1, const float* __restrict__ b2,
    const float* __restrict__ b3, const float* __restrict__ b4,
    const float* __restrict__ a1p)
{
    __shared__ uint4 xt[16*40*2];   // rows h0-4..h0+11, cols w0-4..w0+35 (20 KB)
    const int w0 = blockIdx.x*32, h0 = blockIdx.y*8, bb = blockIdx.z;
    const int tid = threadIdx.x;

    for (int i = tid; i < 16*40; i += 256) {
        int r = i / 40, cc = i % 40;
        int h = h0 - 4 + r, w = w0 - 4 + cc;
        uint4 v0 = make_uint4(0,0,0,0), v1 = v0;
        if (h >= 0 && h < HH_ && w >= 0 && w < WW_) {
            const uint4* src = g_xbits + ((bb*HH_ + h)*WW_ + w)*2;
            v0 = src[0]; v1 = src[1];
        }
        xt[i*2] = v0; xt[i*2+1] = v1;
    }
    __syncthreads();

    const int warp = tid >> 5, lane = tid & 31;
    const int br   = warp >> 1;
    const int o    = (warp & 1)*32 + lane;
    const float bias = ((br==0) ? b1 : (br==1) ? b2 : (br==2) ? b3 : b4)[o];
    const float a1   = a1p[0];
    // tap pattern: (dh,dw) = (k-2)*(sh,sw)
    const int sh = (br >= 2) ? ((br == 2) ? 1 : 2) : 0;
    const int sw = (br <  2) ? ((br == 0) ? 1 : 2) : 0;

    uint4 wr[10];
    {
        const uint4* wsrc = g_wb + ((br*64 + o)*5)*2;
        #pragma unroll
        for (int i = 0; i < 10; i++) wr[i] = wsrc[i];
    }

    unsigned* mout = (unsigned*)g_mbits;
    for (int p = 0; p < 256; p++) {
        int r = p >> 5, cl = p & 31;
        int h = h0 + r, w = w0 + cl;
        int s = 0, nv = 0;
        #pragma unroll
        for (int k = 0; k < 5; k++) {
            int ddh = (k-2)*sh, ddw = (k-2)*sw;
            int hh = h + ddh, ww = w + ddw;
            if (hh >= 0 && hh < HH_ && ww >= 0 && ww < WW_) {   // warp-uniform
                nv++;
                int si = ((r + 4 + ddh)*40 + (cl + 4 + ddw))*2;
                s += pdot8(xt[si], xt[si+1], wr[2*k], wr[2*k+1]);
            }
        }
        float v  = (float)(256*nv - 2*s) + bias;
        float pr = (v >= 0.f) ? v : a1*v;
        unsigned m = __ballot_sync(0xffffffffu, pr >= 0.f);
        if (lane == 0) mout[((bb*HH_ + h)*WW_ + w)*8 + warp] = m;
    }
}

// ---------------------------------------------------------------------------
// Main 3x3 conv + bias + prelu + residual. Block tile: 1 row x 32 pixels.
// 256 threads = 256 out channels; results staged in padded smem so the
// NCHW fp32 store + residual read are coalesced.
__global__ __launch_bounds__(256) void main_conv(
    const float* __restrict__ x, const float* __restrict__ bc,
    const float* __restrict__ a2p, float* __restrict__ out)
{
    __shared__ uint4 xt[3*34*2];        // rows h-1..h+1, cols w0-1..w0+32 (3.2 KB)
    __shared__ int   sInt[256*33];      // [o][32] padded to 33 (33.8 KB)
    const int w0 = blockIdx.x*32, h = blockIdx.y, bb = blockIdx.z;
    const int tid = threadIdx.x;        // = out channel o

    for (int i = tid; i < 3*34; i += 256) {
        int r = i / 34, cc = i % 34;
        int hh = h - 1 + r, ww = w0 - 1 + cc;
        uint4 v0 = make_uint4(0,0,0,0), v1 = v0;
        if (hh >= 0 && hh < HH_ && ww >= 0 && ww < WW_) {
            const uint4* src = g_mbits + ((bb*HH_ + hh)*WW_ + ww)*2;
            v0 = src[0]; v1 = src[1];
        }
        xt[i*2] = v0; xt[i*2+1] = v1;
    }
    __syncthreads();

    uint4 wr[18];
    {
        const uint4* wsrc = g_wcb + tid*18;
        #pragma unroll
        for (int i = 0; i < 18; i++) wr[i] = wsrc[i];
    }

    for (int p = 0; p < 32; p++) {
        int w = w0 + p;
        int s = 0, nv = 0;
        #pragma unroll
        for (int t = 0; t < 9; t++) {
            int ddh = t/3 - 1, ddw = t%3 - 1;
            int hh = h + ddh, ww = w + ddw;
            if (hh >= 0 && hh < HH_ && ww >= 0 && ww < WW_) {   // warp-uniform
                nv++;
                int si = ((ddh + 1)*34 + (p + 1 + ddw))*2;
                s += pdot8(xt[si], xt[si+1], wr[2*t], wr[2*t+1]);
            }
        }
        sInt[tid*33 + p] = 256*nv - 2*s;
    }
    __syncthreads();

    const float a2 = a2p[0];
    for (int i = 0; i < 32; i++) {
        int e = i*256 + tid;
        int o = e >> 5, wl = e & 31;
        float v = (float)sInt[o*33 + wl] + bc[o];
        v = (v >= 0.f) ? v : a2*v;
        size_t xi = (((size_t)bb*CC_ + o)*HH_ + h)*WW_ + w0 + wl;
        out[xi] = v + x[xi];
    }
}

// ---------------------------------------------------------------------------
extern "C" void kernel_launch(void* const* d_in, const int* in_sizes, int n_in,
                              void* d_out, int out_size) {
    const float* x  = (const float*)d_in[0];
    const float* w1 = (const float*)d_in[1];
    const float* b1 = (const float*)d_in[2];
    const float* w2 = (const float*)d_in[3];
    const float* b2 = (const float*)d_in[4];
    const float* w3 = (const float*)d_in[5];
    const float* b3 = (const float*)d_in[6];
    const float* w4 = (const float*)d_in[7];
    const float* b4 = (const float*)d_in[8];
    const float* a1 = (const float*)d_in[9];
    const float* wc = (const float*)d_in[10];
    const float* bc = (const float*)d_in[11];
    const float* a2 = (const float*)d_in[12];
    float* out = (float*)d_out;

    pack_x<<<4096, 256>>>(x);
    pack_w<<<112, 256>>>(w1, w2, w3, w4, wc);
    branch_conv<<<dim3(4,16,8), 256>>>(b1, b2, b3, b4, a1);
    main_conv<<<dim3(4,128,8), 256>>>(x, bc, a2, out);
}